// round 3
// baseline (speedup 1.0000x reference)
#include <cuda_runtime.h>

#define D 128
#define KN 32
#define MAXB 20000

__device__ float g_u[D];
__device__ float g_v[D];
__device__ float g_M[D * D];
__device__ float g_agg[MAXB * D];

// packed f32x2 FMA (Blackwell)
#define FMA2(acc, a, b) \
    asm("fma.rn.f32x2 %0, %1, %2, %0;" : "+l"(acc) : "l"(a), "l"(b))

#define CP_ASYNC16(smem_addr, gptr) \
    asm volatile("cp.async.cg.shared.global [%0], [%1], 16;" \
                 :: "r"(smem_addr), "l"(gptr))
#define CP_ASYNC_WAIT_ALL() \
    do { asm volatile("cp.async.commit_group;"); \
         asm volatile("cp.async.wait_group 0;"); } while (0)

// ---------------------------------------------------------------------------
// Kernel P: precompute. 16 blocks x 128 threads; block g computes M rows
// 8g..8g+7, plus u/v entries for those rows.
//   M[r,:] = kernel1[r,:] @ nw ; u[r]=dot(k1[r],aw[0:D]) ; v[r]=dot(k0[r],aw[D:2D])
// ---------------------------------------------------------------------------
__global__ __launch_bounds__(128) void prep_kernel(
    const float* __restrict__ kernel0,
    const float* __restrict__ kernel1,
    const float* __restrict__ aw,
    const float* __restrict__ nw) {
    extern __shared__ float psm[];
    float* nws = psm;            // D*D (64KB)
    float* k1s = psm + D * D;    // 8*D
    float* k0s = k1s + 8 * D;    // 8*D

    int g = blockIdx.x;
    int t = threadIdx.x;
    int r0 = g * 8;

    const float4* nw4 = (const float4*)nw;
    float4* nws4 = (float4*)nws;
#pragma unroll
    for (int it = 0; it < 32; ++it)
        nws4[it * 128 + t] = nw4[it * 128 + t];
    // 8 rows of kernel1 / kernel0 (each row 128 floats = 32 float4; 256 f4 total)
    {
        const float4* k14 = (const float4*)(kernel1 + r0 * D);
        const float4* k04 = (const float4*)(kernel0 + r0 * D);
        ((float4*)k1s)[t] = k14[t];
        ((float4*)k1s)[t + 128] = k14[t + 128];
        ((float4*)k0s)[t] = k04[t];
        ((float4*)k0s)[t + 128] = k04[t + 128];
    }
    __syncthreads();

    float acc[8] = {0,0,0,0,0,0,0,0};
#pragma unroll 8
    for (int j = 0; j < D; ++j) {
        float nv = nws[j * D + t];
#pragma unroll
        for (int r = 0; r < 8; ++r) acc[r] += k1s[r * D + j] * nv;
    }
#pragma unroll
    for (int r = 0; r < 8; ++r) g_M[(r0 + r) * D + t] = acc[r];

    // u/v: threads 0..7 -> u rows, threads 32..39 -> v rows (diff warps)
    if (t < 8) {
        float s = 0.f;
#pragma unroll 16
        for (int e = 0; e < D; ++e) s += k1s[t * D + e] * aw[e];
        g_u[r0 + t] = s;
    } else if (t >= 32 && t < 40) {
        int r = t - 32;
        float s = 0.f;
#pragma unroll 16
        for (int e = 0; e < D; ++e) s += k0s[r * D + e] * aw[D + e];
        g_v[r0 + r] = s;
    }
}

// ---------------------------------------------------------------------------
// Kernel A: per-target attention. One block (128 threads) per target node.
// ---------------------------------------------------------------------------
__global__ __launch_bounds__(128) void attn_kernel(
    const float* __restrict__ features,
    const int* __restrict__ node,
    const int* __restrict__ neigh,
    int B) {
    __shared__ __align__(16) float nf[KN * D];  // 16 KB
    __shared__ float scores[KN];
    __shared__ float wts[KN];

    int b = blockIdx.x;
    if (b >= B) return;
    int tid  = threadIdx.x;
    int lane = tid & 31;
    int w    = tid >> 5;

    // per-lane neighbor index; row indices distributed via shfl (no smem/sync)
    int nv = __ldg(&neigh[b * KN + lane]);
    int nd = __ldg(&node[b]);

    const float4* f4 = (const float4*)features;
    unsigned nf_s = (unsigned)__cvta_generic_to_shared(nf);

    // gather 32 rows via cp.async: warp w covers rows it*4 + w, lane = col/4
#pragma unroll
    for (int it = 0; it < 8; ++it) {
        int k = it * 4 + w;
        int idx = __shfl_sync(0xffffffffu, nv, k);
        CP_ASYNC16(nf_s + (unsigned)(k * D + lane * 4) * 4u,
                   (const void*)(f4 + (size_t)idx * 32 + lane));
    }

    // node-row dot with v, per-warp redundant (registers only)
    float4 fv = f4[(size_t)nd * 32 + lane];
    float4 vv = ((const float4*)g_v)[lane];
    float sn = fv.x * vv.x + fv.y * vv.y + fv.z * vv.z + fv.w * vv.w;
#pragma unroll
    for (int o = 16; o > 0; o >>= 1) sn += __shfl_xor_sync(0xffffffffu, sn, o);

    CP_ASYNC_WAIT_ALL();
    __syncthreads();

    // scores: thread t handles neighbor k = t>>2, quarter part = t&3
    {
        int k = tid >> 2;
        int part = tid & 3;
        const float4* u4 = (const float4*)g_u;
        const float4* row4 = (const float4*)(nf + k * D) + part * 8;
        float s = 0.f;
#pragma unroll
        for (int j = 0; j < 8; ++j) {
            float4 x = row4[j];
            float4 uu = u4[part * 8 + j];
            s += x.x * uu.x + x.y * uu.y + x.z * uu.z + x.w * uu.w;
        }
        s += __shfl_xor_sync(0xffffffffu, s, 1);
        s += __shfl_xor_sync(0xffffffffu, s, 2);
        if (part == 0) scores[k] = s;    // raw; sn/leaky applied in softmax
    }
    __syncthreads();

    // softmax over K=32 (warp 0); sn already in registers of warp 0
    if (w == 0) {
        float t0 = scores[lane] + sn;
        float sc = (t0 > 0.f) ? t0 : 0.2f * t0;
        float m = sc;
#pragma unroll
        for (int o = 16; o > 0; o >>= 1) m = fmaxf(m, __shfl_xor_sync(0xffffffffu, m, o));
        float e = __expf(sc - m);
        float den = e;
#pragma unroll
        for (int o = 16; o > 0; o >>= 1) den += __shfl_xor_sync(0xffffffffu, den, o);
        wts[lane] = e / den;
    }
    __syncthreads();

    // weighted aggregate of raw features
    float acc = 0.f;
#pragma unroll
    for (int k = 0; k < KN; ++k) acc += wts[k] * nf[k * D + tid];
    g_agg[b * D + tid] = acc;
}

// ---------------------------------------------------------------------------
// Kernel G: out = agg @ M  ([B,128] x [128,128]) — packed f32x2 FMA inner loop
// ---------------------------------------------------------------------------
__global__ __launch_bounds__(128) void out_gemm(float* __restrict__ out, int B) {
    extern __shared__ float sm[];
    float* Ms = sm;            // D*D (64 KB)
    float* aT = sm + D * D;    // D*8 (4 KB), layout [d*8 + r]

    int tid = threadIdx.x;

    float4*       Ms4 = (float4*)Ms;
    const float4* gM4 = (const float4*)g_M;
#pragma unroll
    for (int it = 0; it < 32; ++it) Ms4[it * 128 + tid] = gM4[it * 128 + tid];

    int ngroups = (B + 7) >> 3;
    for (int g = blockIdx.x; g < ngroups; g += gridDim.x) {
        int r0 = g << 3;

        float v[8];
#pragma unroll
        for (int r = 0; r < 8; ++r) {
            int row = r0 + r;
            v[r] = (row < B) ? g_agg[row * D + tid] : 0.f;
        }
        __syncthreads();
        ((float4*)aT)[tid * 2]     = make_float4(v[0], v[1], v[2], v[3]);
        ((float4*)aT)[tid * 2 + 1] = make_float4(v[4], v[5], v[6], v[7]);
        __syncthreads();

        unsigned long long acc01 = 0ull, acc23 = 0ull, acc45 = 0ull, acc67 = 0ull;
#pragma unroll 16
        for (int d = 0; d < D; ++d) {
            float m = Ms[d * D + tid];
            unsigned long long mm;
            asm("mov.b64 %0, {%1, %1};" : "=l"(mm) : "f"(m));
            ulonglong2 p0 = *((const ulonglong2*)(aT + d * 8));
            ulonglong2 p1 = *((const ulonglong2*)(aT + d * 8 + 4));
            FMA2(acc01, p0.x, mm);
            FMA2(acc23, p0.y, mm);
            FMA2(acc45, p1.x, mm);
            FMA2(acc67, p1.y, mm);
        }

        float r_[8];
        asm("mov.b64 {%0, %1}, %2;" : "=f"(r_[0]), "=f"(r_[1]) : "l"(acc01));
        asm("mov.b64 {%0, %1}, %2;" : "=f"(r_[2]), "=f"(r_[3]) : "l"(acc23));
        asm("mov.b64 {%0, %1}, %2;" : "=f"(r_[4]), "=f"(r_[5]) : "l"(acc45));
        asm("mov.b64 {%0, %1}, %2;" : "=f"(r_[6]), "=f"(r_[7]) : "l"(acc67));
#pragma unroll
        for (int r = 0; r < 8; ++r) {
            int row = r0 + r;
            if (row < B) out[row * D + tid] = r_[r];
        }
    }
}

// ---------------------------------------------------------------------------
extern "C" void kernel_launch(void* const* d_in, const int* in_sizes, int n_in,
                              void* d_out, int out_size) {
    const float* features = (const float*)d_in[0];
    const int*   node     = (const int*)d_in[1];
    const int*   neigh    = (const int*)d_in[2];
    const float* kern0    = (const float*)d_in[3];
    const float* kern1    = (const float*)d_in[4];
    const float* aw       = (const float*)d_in[5];
    const float* nw       = (const float*)d_in[6];
    float*       out      = (float*)d_out;

    int B = in_sizes[1];
    if (B > MAXB) B = MAXB;

    const int prep_smem = (D * D + 16 * D) * sizeof(float);   // 72 KB
    cudaFuncSetAttribute(prep_kernel, cudaFuncAttributeMaxDynamicSharedMemorySize, prep_smem);
    prep_kernel<<<16, D, prep_smem>>>(kern0, kern1, aw, nw);

    attn_kernel<<<B, D>>>(features, node, neigh, B);

    const int gemm_smem = (D * D + D * 8) * sizeof(float);    // 68 KB
    cudaFuncSetAttribute(out_gemm, cudaFuncAttributeMaxDynamicSharedMemorySize, gemm_smem);
    out_gemm<<<444, D, gemm_smem>>>(out, B);
}

// round 5
// speedup vs baseline: 1.3511x; 1.3511x over previous
#include <cuda_runtime.h>

#define D 128
#define KN 32
#define MAXB 20000

__device__ float g_u[D];
__device__ float g_v[D];
__device__ float g_M[D * D];
__device__ float g_agg[MAXB * D];

// ---------------------------------------------------------------------------
// Kernel P1: u/v precompute. 2 blocks x 128 threads.
// Block 0: u[d] = dot(kernel1[d,:], aw[0:D])
// Block 1: v[d] = dot(kernel0[d,:], aw[D:2D])
// Warp w handles rows w*32 .. w*32+31 (4 warps x 32 = all 128 rows).
// ---------------------------------------------------------------------------
__global__ __launch_bounds__(128) void prep_uv(
    const float* __restrict__ kernel0,
    const float* __restrict__ kernel1,
    const float* __restrict__ aw) {
    int t    = threadIdx.x;
    int lane = t & 31;
    int w    = t >> 5;

    const float* mat = (blockIdx.x == 0) ? kernel1 : kernel0;
    const float* a   = aw + blockIdx.x * D;
    float*       out = (blockIdx.x == 0) ? g_u : g_v;

    float4 av = ((const float4*)a)[lane];
    const float4* m4 = (const float4*)mat;
#pragma unroll
    for (int j = 0; j < 32; ++j) {
        int r = w * 32 + j;
        float4 x = m4[r * 32 + lane];
        float s = x.x * av.x + x.y * av.y + x.z * av.z + x.w * av.w;
#pragma unroll
        for (int o = 16; o > 0; o >>= 1) s += __shfl_xor_sync(0xffffffffu, s, o);
        if (lane == 0) out[r] = s;
    }
}

// ---------------------------------------------------------------------------
// Kernel P2: M precompute (R2-measured 8.6us form). 128 blocks x 128 threads.
// Block b stages nw (64KB) + kernel1 row b, computes M[b,:] = krow @ nw.
// ---------------------------------------------------------------------------
__global__ __launch_bounds__(128) void prep_M(
    const float* __restrict__ kernel1,
    const float* __restrict__ nw) {
    extern __shared__ float psm[];
    float* nws  = psm;          // D*D floats (64KB)
    float* krow = psm + D * D;  // D floats

    int b = blockIdx.x;
    int t = threadIdx.x;

    krow[t] = kernel1[b * D + t];
    const float4* nw4  = (const float4*)nw;
    float4*       nws4 = (float4*)nws;
#pragma unroll
    for (int it = 0; it < 32; ++it)
        nws4[it * 128 + t] = nw4[it * 128 + t];
    __syncthreads();

    float acc = 0.f;
#pragma unroll 16
    for (int j = 0; j < D; ++j)
        acc += krow[j] * nws[j * D + t];
    g_M[b * D + t] = acc;
}

// ---------------------------------------------------------------------------
// Kernel A: per-target attention (exact R1 structure — measured best).
// ---------------------------------------------------------------------------
__global__ __launch_bounds__(128) void attn_kernel(
    const float* __restrict__ features,
    const int* __restrict__ node,
    const int* __restrict__ neigh,
    int B) {
    __shared__ float nf[KN * D];   // 16 KB: 32 neighbor rows
    __shared__ float fnode[D];
    __shared__ float scores[KN];
    __shared__ float wts[KN];

    int b = blockIdx.x;
    if (b >= B) return;
    int tid  = threadIdx.x;
    int lane = tid & 31;
    int w    = tid >> 5;

    const float4* f4  = (const float4*)features;
    float4*       nf4 = (float4*)nf;

#pragma unroll
    for (int it = 0; it < 8; ++it) {
        int i  = it * 128 + tid;
        int k  = i >> 5;
        int c  = i & 31;
        int nb = __ldg(&neigh[b * KN + k]);
        nf4[i] = f4[(size_t)nb * 32 + c];
    }
    if (tid < 32) {
        int nd = __ldg(&node[b]);
        ((float4*)fnode)[tid] = f4[(size_t)nd * 32 + tid];
    }
    __syncthreads();

    float4 fv = ((const float4*)fnode)[lane];
    float4 vv = ((const float4*)g_v)[lane];
    float sn = fv.x * vv.x + fv.y * vv.y + fv.z * vv.z + fv.w * vv.w;
#pragma unroll
    for (int o = 16; o > 0; o >>= 1) sn += __shfl_xor_sync(0xffffffffu, sn, o);

    float4 uu = ((const float4*)g_u)[lane];
#pragma unroll
    for (int j = 0; j < 8; ++j) {
        int k = w * 8 + j;
        float4 x = nf4[k * 32 + lane];
        float s = x.x * uu.x + x.y * uu.y + x.z * uu.z + x.w * uu.w;
#pragma unroll
        for (int o = 16; o > 0; o >>= 1) s += __shfl_xor_sync(0xffffffffu, s, o);
        if (lane == 0) {
            float t = s + sn;
            scores[k] = (t > 0.f) ? t : 0.2f * t;   // leaky_relu alpha=0.2
        }
    }
    __syncthreads();

    if (w == 0) {
        float sc = scores[lane];
        float m = sc;
#pragma unroll
        for (int o = 16; o > 0; o >>= 1) m = fmaxf(m, __shfl_xor_sync(0xffffffffu, m, o));
        float e = __expf(sc - m);
        float den = e;
#pragma unroll
        for (int o = 16; o > 0; o >>= 1) den += __shfl_xor_sync(0xffffffffu, den, o);
        wts[lane] = e / den;
    }
    __syncthreads();

    float acc = 0.f;
#pragma unroll
    for (int k = 0; k < KN; ++k) acc += wts[k] * nf[k * D + tid];
    g_agg[b * D + tid] = acc;
}

// ---------------------------------------------------------------------------
// Kernel G: out = agg @ M (exact R1 structure — float4 inner loop).
// ---------------------------------------------------------------------------
__global__ __launch_bounds__(128) void out_gemm(float* __restrict__ out, int B) {
    extern __shared__ float sm[];
    float* Ms = sm;            // D*D floats (64 KB)
    float* aT = sm + D * D;    // D*8 floats (4 KB), layout [d*8 + r]

    int tid = threadIdx.x;

    float4*       Ms4 = (float4*)Ms;
    const float4* gM4 = (const float4*)g_M;
#pragma unroll
    for (int it = 0; it < 32; ++it) Ms4[it * 128 + tid] = gM4[it * 128 + tid];

    int ngroups = (B + 7) >> 3;
    for (int g = blockIdx.x; g < ngroups; g += gridDim.x) {
        int r0 = g << 3;

        float v[8];
#pragma unroll
        for (int r = 0; r < 8; ++r) {
            int row = r0 + r;
            v[r] = (row < B) ? g_agg[row * D + tid] : 0.f;
        }
        __syncthreads();
        ((float4*)aT)[tid * 2]     = make_float4(v[0], v[1], v[2], v[3]);
        ((float4*)aT)[tid * 2 + 1] = make_float4(v[4], v[5], v[6], v[7]);
        __syncthreads();

        float acc[8] = {0.f, 0.f, 0.f, 0.f, 0.f, 0.f, 0.f, 0.f};
#pragma unroll 16
        for (int d = 0; d < D; ++d) {
            float m = Ms[d * D + tid];
            float4 a0 = ((const float4*)aT)[d * 2];
            float4 a1 = ((const float4*)aT)[d * 2 + 1];
            acc[0] += a0.x * m; acc[1] += a0.y * m;
            acc[2] += a0.z * m; acc[3] += a0.w * m;
            acc[4] += a1.x * m; acc[5] += a1.y * m;
            acc[6] += a1.z * m; acc[7] += a1.w * m;
        }
#pragma unroll
        for (int r = 0; r < 8; ++r) {
            int row = r0 + r;
            if (row < B) out[row * D + tid] = acc[r];
        }
    }
}

// ---------------------------------------------------------------------------
extern "C" void kernel_launch(void* const* d_in, const int* in_sizes, int n_in,
                              void* d_out, int out_size) {
    const float* features = (const float*)d_in[0];
    const int*   node     = (const int*)d_in[1];
    const int*   neigh    = (const int*)d_in[2];
    const float* kern0    = (const float*)d_in[3];
    const float* kern1    = (const float*)d_in[4];
    const float* aw       = (const float*)d_in[5];
    const float* nw       = (const float*)d_in[6];
    float*       out      = (float*)d_out;

    int B = in_sizes[1];
    if (B > MAXB) B = MAXB;

    // Order: uv -> attn -> M -> gemm. attn only depends on u,v; M only
    // gates the gemm. (Also shifts the ncu capture slot onto attn.)
    prep_uv<<<2, D>>>(kern0, kern1, aw);

    attn_kernel<<<B, D>>>(features, node, neigh, B);

    const int prepM_smem = (D * D + D) * sizeof(float);       // ~66 KB
    cudaFuncSetAttribute(prep_M, cudaFuncAttributeMaxDynamicSharedMemorySize, prepM_smem);
    prep_M<<<D, D, prepM_smem>>>(kern1, nw);

    const int gemm_smem = (D * D + D * 8) * sizeof(float);    // 68 KB
    cudaFuncSetAttribute(out_gemm, cudaFuncAttributeMaxDynamicSharedMemorySize, gemm_smem);
    out_gemm<<<444, D, gemm_smem>>>(out, B);
}